// round 14
// baseline (speedup 1.0000x reference)
#include <cuda_runtime.h>
#include <cstdint>
#include <math.h>

// ============================================================================
// AttendAndSpell — persistent kernel, 148 blocks x 512 threads (16 warps/SM).
// SMEM-resident gate weights; 2-row x depth-2 attention pipeline; 4 phases/step.
// ============================================================================

#define B_   128
#define R_   512
#define HID_ 512
#define VOC_ 64
#define T_   128
#define NB   148
#define NT   512
#define NTH  (NB * NT)

// dyn smem (floats): WI0s[0,16384) WI1s[16384,32768) AsG[32768,36864)
#define SMEM_DYN (36864 * 4)

// ---------------- scratch ----------------
__device__ float g_hp  [(size_t)B_ * R_ * HID_];      // 134 MB
__device__ float g_psiT[512 * 512];
__device__ float g_phiT[512 * 512];                   // [k][j]
__device__ float g_outT[512 * 64];
__device__ float g_ohI [64 * 2048];
__device__ float g_b0I [2048];
__device__ float g_b1I [2048];
__device__ float g_sq  [B_ * 512];
__device__ float g_XA  [2][B_ * 1024];                // [c | s0]
__device__ float g_XB  [2][B_ * 1024];                // [s0 | s1]
__device__ float g_S1  [B_ * 512];
__device__ float g_cs0 [B_ * 512];
__device__ float g_cs1 [B_ * 512];
__device__ int   g_z   [B_];
__device__ uint2 g_keys[T_];
__device__ unsigned g_bcnt = 0;
__device__ unsigned g_bgen = 0;

// ---------------- grid barrier (proven) ----------------
__device__ __forceinline__ void gbar() {
    __syncthreads();
    if (threadIdx.x == 0) {
        unsigned gen = *((volatile unsigned*)&g_bgen);
        __threadfence();
        if (atomicAdd(&g_bcnt, 1u) == NB - 1u) {
            atomicExch(&g_bcnt, 0u);
            __threadfence();
            atomicAdd(&g_bgen, 1u);
        } else {
            while (*((volatile unsigned*)&g_bgen) == gen) { __nanosleep(32); }
        }
        __threadfence();
    }
    __syncthreads();
}

// ---------------- Threefry-2x32 (bit-exact, proven) ----------------
__device__ __forceinline__ void tf2x32(uint32_t k0, uint32_t k1,
                                       uint32_t x0, uint32_t x1,
                                       uint32_t& o0, uint32_t& o1) {
    uint32_t k2 = k0 ^ k1 ^ 0x1BD11BDAu;
    x0 += k0; x1 += k1;
#define RR(r) { x0 += x1; x1 = (x1 << (r)) | (x1 >> (32 - (r))); x1 ^= x0; }
    RR(13) RR(15) RR(26) RR(6)   x0 += k1; x1 += k2 + 1u;
    RR(17) RR(29) RR(16) RR(24)  x0 += k2; x1 += k0 + 2u;
    RR(13) RR(15) RR(26) RR(6)   x0 += k0; x1 += k1 + 3u;
    RR(17) RR(29) RR(16) RR(24)  x0 += k1; x1 += k2 + 4u;
    RR(13) RR(15) RR(26) RR(6)   x0 += k2; x1 += k0 + 5u;
#undef RR
    o0 = x0; o1 = x1;
}

__device__ __forceinline__ float bits_to_unit(uint32_t bits) {
    return __uint_as_float((bits >> 9) | 0x3f800000u) - 1.0f;
}

__device__ __forceinline__ float sigm(float x) { return 1.f / (1.f + expf(-x)); }

// ---------------- setup ----------------
__device__ void phase_setup(const float* __restrict__ phi_w, const float* __restrict__ psi_w,
                            const float* __restrict__ phi_b,
                            const float* __restrict__ w_ih0,
                            const float* __restrict__ b_ih0, const float* __restrict__ b_hh0,
                            const float* __restrict__ b_ih1, const float* __restrict__ b_hh1,
                            const float* __restrict__ out_w, const int* __restrict__ y) {
    int gt = blockIdx.x * NT + threadIdx.x;
    for (int i = gt; i < 512 * 512; i += NTH) {
        int k = i >> 9, j = i & 511;
        g_psiT[i] = psi_w[j * 512 + k];
        g_phiT[i] = phi_w[j * 512 + k];
    }
    for (int i = gt; i < 64 * 2048; i += NTH) {
        int v = i >> 11, col = i & 2047, d = col >> 2, g = col & 3;
        g_ohI[i] = w_ih0[(g * 512 + d) * 576 + v];
    }
    for (int i = gt; i < 2048; i += NTH) {
        int d = i >> 2, g = i & 3;
        g_b0I[i] = b_ih0[g * 512 + d] + b_hh0[g * 512 + d];
        g_b1I[i] = b_ih1[g * 512 + d] + b_hh1[g * 512 + d];
    }
    for (int i = gt; i < 512 * 64; i += NTH) {
        int k = i >> 6, v = i & 63;
        g_outT[i] = out_w[v * 512 + k];
    }
    for (int i = gt; i < B_ * 1024; i += NTH) {
        g_XA[0][i] = 0.f; g_XA[1][i] = 0.f;
        g_XB[0][i] = 0.f; g_XB[1][i] = 0.f;
    }
    for (int i = gt; i < B_ * 512; i += NTH) {
        g_cs0[i] = 0.f; g_cs1[i] = 0.f; g_S1[i] = 0.f;
        g_sq[i] = phi_b[i & 511];               // s1=0 -> sq = phi_b
    }
    if (gt < T_) {
        uint32_t a, b;
        tf2x32(0u, 42u, 0u, (uint32_t)gt, a, b);
        g_keys[gt] = make_uint2(a, b);
    }
    if (gt < B_) g_z[gt] = y[gt * (T_ + 1)];
}

// ---------------- hp precompute: 64x64 tiles, 512 threads -------------------
__device__ void gemm64(float* sbuf, const float* __restrict__ A,
                       const float* __restrict__ Bm, float* __restrict__ C,
                       const float* __restrict__ bias) {
    float (*As)[68] = (float(*)[68])sbuf;
    float (*Bs)[64] = (float(*)[64])(sbuf + 16 * 68);
    int tid = threadIdx.x;
    int r   = tid >> 3, kc = (tid & 7) << 1;     // A: 64 rows x 16k, float2/thread
    int bkk = tid >> 5, bnc = (tid & 31) << 1;   // B: 16k x 64, float2/thread
    int tx  = tid & 15, ty = tid >> 4;           // out: 2 rows x 4 cols
    for (int tile = blockIdx.x; tile < 1024 * 8; tile += NB) {
        int m0 = (tile >> 3) << 6;
        int n0 = (tile & 7) << 6;
        float acc[8];
#pragma unroll
        for (int i = 0; i < 8; i++) acc[i] = 0.f;
        const float* Ap = A + (size_t)(m0 + r) * 512 + kc;
        const float* Bp = Bm + (size_t)bkk * 512 + n0 + bnc;
        float2 av = *(const float2*)(Ap);
        float2 bv = *(const float2*)(Bp);
        for (int k0 = 0; k0 < 512; k0 += 16) {
            __syncthreads();
            As[kc][r] = av.x; As[kc + 1][r] = av.y;
            Bs[bkk][bnc] = bv.x; Bs[bkk][bnc + 1] = bv.y;
            __syncthreads();
            if (k0 + 16 < 512) {
                av = *(const float2*)(Ap + k0 + 16);
                bv = *(const float2*)(Bp + (size_t)(k0 + 16) * 512);
            }
#pragma unroll
            for (int kk = 0; kk < 16; kk++) {
                float2 a2 = *(const float2*)&As[kk][ty << 1];
                float4 b4 = *(const float4*)&Bs[kk][tx << 2];
                acc[0] = fmaf(a2.x, b4.x, acc[0]); acc[1] = fmaf(a2.x, b4.y, acc[1]);
                acc[2] = fmaf(a2.x, b4.z, acc[2]); acc[3] = fmaf(a2.x, b4.w, acc[3]);
                acc[4] = fmaf(a2.y, b4.x, acc[4]); acc[5] = fmaf(a2.y, b4.y, acc[5]);
                acc[6] = fmaf(a2.y, b4.z, acc[6]); acc[7] = fmaf(a2.y, b4.w, acc[7]);
            }
        }
        float4 bb = *(const float4*)&bias[n0 + (tx << 2)];
#pragma unroll
        for (int i = 0; i < 2; i++) {
            float4 rr;
            rr.x = acc[i * 4 + 0] + bb.x; rr.y = acc[i * 4 + 1] + bb.y;
            rr.z = acc[i * 4 + 2] + bb.z; rr.w = acc[i * 4 + 3] + bb.w;
            *(float4*)&C[(size_t)(m0 + (ty << 1) + i) * 512 + n0 + (tx << 2)] = rr;
        }
    }
}

// ---------------- gates GEMM (128 x 16 cols, K=1024) + LSTM epilogue --------
// 512 threads: ty = batch row (0..127), tx = d within tile (0..3).
__device__ void gemm_gates(const float* __restrict__ A, const float* __restrict__ WIs,
                           float* As, const float* __restrict__ bI,
                           float* __restrict__ cs,
                           float* __restrict__ o1, int ld1,
                           float* __restrict__ o2, int ld2,
                           int n0, int layer0) {
    int tid = threadIdx.x;
    int ty = tid >> 2;                   // 0..127
    int tx = tid & 3;
    int skoff = tx << 2;                 // 0,4,8,12
    float acc0[4] = {0.f, 0.f, 0.f, 0.f};
    const float* Arow = A + ty * 1024 + skoff;
    float4 pa = *(const float4*)(Arow);
    {
        float* dst = As;
        dst[(skoff + 0) * 128 + ty] = pa.x; dst[(skoff + 1) * 128 + ty] = pa.y;
        dst[(skoff + 2) * 128 + ty] = pa.z; dst[(skoff + 3) * 128 + ty] = pa.w;
    }
    for (int k0 = 0; k0 < 1024; k0 += 16) {
        int buf = (k0 >> 4) & 1;
        __syncthreads();
        if (k0 + 16 < 1024) {
            pa = *(const float4*)(Arow + k0 + 16);
            float* dst = As + (buf ^ 1) * 2048;
            dst[(skoff + 0) * 128 + ty] = pa.x; dst[(skoff + 1) * 128 + ty] = pa.y;
            dst[(skoff + 2) * 128 + ty] = pa.z; dst[(skoff + 3) * 128 + ty] = pa.w;
        }
        const float* Ab = As + buf * 2048;
#pragma unroll
        for (int kk = 0; kk < 16; kk++) {
            float a0 = Ab[kk * 128 + ty];
            float4 wv = *(const float4*)&WIs[(k0 + kk) * 16 + (tx << 2)];
            acc0[0] = fmaf(a0, wv.x, acc0[0]); acc0[1] = fmaf(a0, wv.y, acc0[1]);
            acc0[2] = fmaf(a0, wv.z, acc0[2]); acc0[3] = fmaf(a0, wv.w, acc0[3]);
        }
    }
    int d = (n0 >> 2) + tx;
    float4 bb = *(const float4*)&bI[n0 + (tx << 2)];
    float gi = acc0[0] + bb.x;
    float gf = acc0[1] + bb.y;
    float gg = acc0[2] + bb.z;
    float go = acc0[3] + bb.w;
    if (layer0) {
        float4 oh = *(const float4*)&g_ohI[(size_t)g_z[ty] * 2048 + n0 + (tx << 2)];
        gi += oh.x; gf += oh.y; gg += oh.z; go += oh.w;
    }
    float ii = sigm(gi), ff = sigm(gf), g2 = tanhf(gg), oo = sigm(go);
    float c = ff * cs[ty * 512 + d] + ii * g2;
    cs[ty * 512 + d] = c;
    float hh = oo * tanhf(c);
    o1[ty * ld1 + d] = hh;
    o2[ty * ld2 + d] = hh;
}

// ---------------- attention: 16 warps x 32 rows, 2-row x depth-2 pipeline ---
#define ATT_LOAD(V, ro) do {                                                  \
    const float* rp_ = hpw + (size_t)(ro) * 512;                              \
    _Pragma("unroll") for (int i_ = 0; i_ < 2; i_++)                          \
    _Pragma("unroll") for (int j_ = 0; j_ < 4; j_++)                          \
        V[i_][j_] = *(const float4*)(rp_ + i_ * 512 + j_ * 128 + (lane << 2));\
} while (0)

#define ATT_PROC(V) do {                                                      \
    float d0 = 0.f, d1 = 0.f;                                                 \
    _Pragma("unroll") for (int j_ = 0; j_ < 4; j_++) {                        \
        d0 = fmaf(qf[j_].x, V[0][j_].x, d0); d0 = fmaf(qf[j_].y, V[0][j_].y, d0); \
        d0 = fmaf(qf[j_].z, V[0][j_].z, d0); d0 = fmaf(qf[j_].w, V[0][j_].w, d0); \
        d1 = fmaf(qf[j_].x, V[1][j_].x, d1); d1 = fmaf(qf[j_].y, V[1][j_].y, d1); \
        d1 = fmaf(qf[j_].z, V[1][j_].z, d1); d1 = fmaf(qf[j_].w, V[1][j_].w, d1); } \
    _Pragma("unroll") for (int off_ = 16; off_ > 0; off_ >>= 1) {             \
        d0 += __shfl_xor_sync(0xffffffffu, d0, off_);                         \
        d1 += __shfl_xor_sync(0xffffffffu, d1, off_); }                       \
    float mn_ = fmaxf(m, fmaxf(d0, d1));                                      \
    float corr_ = __expf(m - mn_);                                            \
    float p0_ = __expf(d0 - mn_), p1_ = __expf(d1 - mn_);                     \
    s = s * corr_ + p0_ + p1_;                                                \
    _Pragma("unroll") for (int j_ = 0; j_ < 4; j_++) {                        \
        cacc[j_].x = fmaf(p0_, V[0][j_].x, fmaf(p1_, V[1][j_].x, cacc[j_].x * corr_)); \
        cacc[j_].y = fmaf(p0_, V[0][j_].y, fmaf(p1_, V[1][j_].y, cacc[j_].y * corr_)); \
        cacc[j_].z = fmaf(p0_, V[0][j_].z, fmaf(p1_, V[1][j_].z, cacc[j_].z * corr_)); \
        cacc[j_].w = fmaf(p0_, V[0][j_].w, fmaf(p1_, V[1][j_].w, cacc[j_].w * corr_)); } \
    m = mn_;                                                                  \
} while (0)

__device__ void attn_block(float* __restrict__ XAc) {
    __shared__ float sm_v[16][512];
    __shared__ float sm_ms[32];
    int b = blockIdx.x;
    int tid = threadIdx.x, lane = tid & 31, w = tid >> 5;   // 16 warps
    const float* sqb = g_sq + b * 512;
    float4 qf[4];
#pragma unroll
    for (int j = 0; j < 4; j++)
        qf[j] = *(const float4*)(sqb + j * 128 + (lane << 2));
    const float* hpw = g_hp + (size_t)b * (R_ * HID_) + (size_t)w * 32 * 512;
    float m = -INFINITY, s = 0.f;
    float4 cacc[4];
#pragma unroll
    for (int j = 0; j < 4; j++) cacc[j] = make_float4(0.f, 0.f, 0.f, 0.f);

    float4 va[2][4], vb[2][4];
    ATT_LOAD(va, 0);
    for (int p = 0; p < 16; p += 2) {
        ATT_LOAD(vb, (p + 1) * 2);
        ATT_PROC(va);
        if (p + 2 < 16) ATT_LOAD(va, (p + 2) * 2);
        ATT_PROC(vb);
    }
#pragma unroll
    for (int j = 0; j < 4; j++)
        *(float4*)&sm_v[w][j * 128 + (lane << 2)] = cacc[j];
    if (lane == 0) { sm_ms[w] = m; sm_ms[16 + w] = s; }
    __syncthreads();
    float M = sm_ms[0];
#pragma unroll
    for (int i = 1; i < 16; i++) M = fmaxf(M, sm_ms[i]);
    float we[16]; float S = 0.f;
#pragma unroll
    for (int i = 0; i < 16; i++) { we[i] = __expf(sm_ms[i] - M); S = fmaf(sm_ms[16 + i], we[i], S); }
    float inv = 1.f / S;
    {
        int c = tid;                      // 512 threads, 1 column each
        float a = 0.f;
#pragma unroll
        for (int i = 0; i < 16; i++) a = fmaf(we[i], sm_v[i][c], a);
        XAc[b * 1024 + c] = a * inv;
    }
}

// ---------------- sq: 128 tiles of 32 rows x 16 cols, K=512 -----------------
__device__ void sq_small(const float* __restrict__ phi_b) {
    int bx = blockIdx.x;                 // 0..127
    int m0 = (bx & 3) << 5;
    int n0s = (bx >> 2) << 4;
    int tid = threadIdx.x;
    int r = tid >> 4;                    // 0..31
    int c = tid & 15;                    // 0..15
    const float* a = g_S1 + (m0 + r) * 512;
    float acc = phi_b[n0s + c];
    float accb = 0.f;
#pragma unroll 8
    for (int k = 0; k < 512; k += 2) {
        acc  = fmaf(a[k],     g_phiT[(size_t)k * 512 + n0s + c],       acc);
        accb = fmaf(a[k + 1], g_phiT[(size_t)(k + 1) * 512 + n0s + c], accb);
    }
    g_sq[(m0 + r) * 512 + n0s + c] = acc + accb;
}

// ---------------- logits + sampler (bit-exact threefry path) ----------------
__device__ void logits_sample(int t, const float* __restrict__ out_b,
                              const int* __restrict__ y, float* __restrict__ out) {
    __shared__ float sl[8][64];
    __shared__ float sg2[64];
    int b = blockIdx.x;
    int tid = threadIdx.x, v = tid & 63, part = tid >> 6;   // 8 parts x 64 k
    const float* s1 = g_S1 + b * 512 + part * 64;
    const float* ot = g_outT + part * 64 * 64 + v;
    float a0 = 0.f, a1 = 0.f;
#pragma unroll 4
    for (int k = 0; k < 64; k += 2) {
        a0 = fmaf(s1[k],     ot[k * 64],       a0);
        a1 = fmaf(s1[k + 1], ot[(k + 1) * 64], a1);
    }
    sl[part][v] = a0 + a1;
    __syncthreads();
    uint2 kt = g_keys[t];
    uint32_t k1a, k1b;
    tf2x32(kt.x, kt.y, 0u, 0u, k1a, k1b);
    if (tid < 64) {
        float logit = sl[0][tid] + sl[1][tid] + sl[2][tid] + sl[3][tid]
                    + sl[4][tid] + sl[5][tid] + sl[6][tid] + sl[7][tid] + out_b[tid];
        out[((size_t)b * T_ + t) * VOC_ + tid] = logit;
        uint32_t r0, r1;
        tf2x32(k1a, k1b, 0u, (uint32_t)(b * VOC_ + tid), r0, r1);
        float f = bits_to_unit(r0 ^ r1);
        float u2 = fmaxf(f, 1.17549435e-38f);
        sg2[tid] = logit + (-logf(-logf(u2)));
    }
    __syncthreads();
    if (tid < 32) {
        float v0 = sg2[tid], v1 = sg2[tid + 32];
        int i0 = tid;
        if (v1 > v0) { v0 = v1; i0 = tid + 32; }
#pragma unroll
        for (int off = 16; off > 0; off >>= 1) {
            float ov = __shfl_down_sync(0xffffffffu, v0, off);
            int   oi = __shfl_down_sync(0xffffffffu, i0, off);
            if (ov > v0 || (ov == v0 && oi < i0)) { v0 = ov; i0 = oi; }
        }
        if (tid == 0) {
            uint32_t k2a, k2b, r0, r1;
            tf2x32(kt.x, kt.y, 0u, 1u, k2a, k2b);
            tf2x32(k2a, k2b, 0u, (uint32_t)b, r0, r1);
            float f = fmaxf(bits_to_unit(r0 ^ r1), 0.0f);
            g_z[b] = (f < 0.1f) ? i0 : y[b * (T_ + 1) + t + 1];
        }
    }
    __syncthreads();
}

// ============================================================================
__global__ void __launch_bounds__(NT, 1)
aas_persistent(const float* __restrict__ h,
               const float* __restrict__ phi_w, const float* __restrict__ phi_b,
               const float* __restrict__ psi_w, const float* __restrict__ psi_b,
               const float* __restrict__ w_ih0, const float* __restrict__ w_hh0,
               const float* __restrict__ b_ih0, const float* __restrict__ b_hh0,
               const float* __restrict__ w_ih1, const float* __restrict__ w_hh1,
               const float* __restrict__ b_ih1, const float* __restrict__ b_hh1,
               const float* __restrict__ out_w, const float* __restrict__ out_b,
               const int* __restrict__ y, float* __restrict__ out) {
    extern __shared__ float sbuf[];
    int tid = threadIdx.x;
    int bx = blockIdx.x;

    phase_setup(phi_w, psi_w, phi_b, w_ih0, b_ih0, b_hh0, b_ih1, b_hh1, out_w, y);
    gbar();

    gemm64(sbuf, h, g_psiT, g_hp, psi_b);    // hp = h @ psi^T + psi_b
    __syncthreads();                          // sbuf scratch done before residency

    if (bx < B_) {
        int n0 = bx * 16, d0 = n0 >> 2;
        float* WI0s = sbuf;
        float* WI1s = sbuf + 16384;
        for (int i = tid; i < 16 * 1024; i += NT) {
            int c = i >> 10, k = i & 1023;
            int g = c & 3, d = d0 + (c >> 2);
            int oc = g * 512 + d;
            WI0s[k * 16 + c] = (k < 512) ? w_ih0[oc * 576 + 64 + k]
                                         : w_hh0[oc * 512 + (k - 512)];
            WI1s[k * 16 + c] = (k < 512) ? w_ih1[oc * 512 + k]
                                         : w_hh1[oc * 512 + (k - 512)];
        }
    }
    gbar();

    float* AsG = sbuf + 32768;
    int n0 = bx * 16;

    for (int t = 0; t < T_; t++) {
        float* XAc = g_XA[t & 1];
        float* XAn = g_XA[(t + 1) & 1];
        float* XBc = g_XB[t & 1];
        float* XBn = g_XB[(t + 1) & 1];
        // phase 1: attention -> c into XAc[:, :512]
        if (bx < B_) attn_block(XAc);
        gbar();
        // phase 2: gates0 + LSTM0 -> s0 into XBc[:, :512] and XAn[:, 512:]
        if (bx < B_)
            gemm_gates(XAc, sbuf, AsG, g_b0I, g_cs0, XBc, 1024, XAn + 512, 1024, n0, 1);
        gbar();
        // phase 3: gates1 + LSTM1 -> s1 into XBn[:, 512:] and S1
        if (bx < B_)
            gemm_gates(XBc, sbuf + 16384, AsG, g_b1I, g_cs1, XBn + 512, 1024, g_S1, 512, n0, 0);
        gbar();
        // phase 4: logits + sampler + next-step sq (blocks < 128)
        if (bx < B_) {
            logits_sample(t, out_b, y, out);
            sq_small(phi_b);
        }
        gbar();
    }
}

extern "C" void kernel_launch(void* const* d_in, const int* in_sizes, int n_in,
                              void* d_out, int out_size) {
    const float* h     = (const float*)d_in[0];
    const float* phi_w = (const float*)d_in[1];
    const float* phi_b = (const float*)d_in[2];
    const float* psi_w = (const float*)d_in[3];
    const float* psi_b = (const float*)d_in[4];
    const float* w_ih0 = (const float*)d_in[5];
    const float* w_hh0 = (const float*)d_in[6];
    const float* b_ih0 = (const float*)d_in[7];
    const float* b_hh0 = (const float*)d_in[8];
    const float* w_ih1 = (const float*)d_in[9];
    const float* w_hh1 = (const float*)d_in[10];
    const float* b_ih1 = (const float*)d_in[11];
    const float* b_hh1 = (const float*)d_in[12];
    const float* out_w = (const float*)d_in[13];
    const float* out_b = (const float*)d_in[14];
    const int*   y     = (const int*)d_in[15];
    float* out = (float*)d_out;

    cudaFuncSetAttribute(aas_persistent,
                         cudaFuncAttributeMaxDynamicSharedMemorySize, SMEM_DYN);
    aas_persistent<<<NB, NT, SMEM_DYN>>>(h, phi_w, phi_b, psi_w, psi_b,
                                         w_ih0, w_hh0, b_ih0, b_hh0,
                                         w_ih1, w_hh1, b_ih1, b_hh1,
                                         out_w, out_b, y, out);
}

// round 15
// speedup vs baseline: 1.1680x; 1.1680x over previous
#include <cuda_runtime.h>
#include <cstdint>
#include <math.h>

// ============================================================================
// AttendAndSpell — persistent kernel, 148 x 256, 1 block/SM.
// 3 barriers/step: [qGEMV+attention | sampler on idle blocks] -> gates0 -> gates1.
// ============================================================================

#define B_   128
#define R_   512
#define HID_ 512
#define VOC_ 64
#define T_   128
#define NB   148
#define NT   256
#define NTH  (NB * NT)

// dyn smem (floats): WI0s[0,16384) WI1s[16384,32768) AsG[32768,37888)
#define SMEM_DYN (37888 * 4)

// ---------------- scratch ----------------
__device__ float g_hp  [(size_t)B_ * R_ * HID_];      // 134 MB
__device__ float g_psiT[512 * 512];
__device__ float g_phiT[512 * 512];                   // [k][j]
__device__ float g_outT[512 * 64];
__device__ float g_ohI [64 * 2048];
__device__ float g_b0I [2048];
__device__ float g_b1I [2048];
__device__ float g_XA  [2][B_ * 1024];                // [c | s0]
__device__ float g_XB  [2][B_ * 1024];                // [s0 | s1]
__device__ float g_S1  [B_ * 512];
__device__ float g_cs0 [B_ * 512];
__device__ float g_cs1 [B_ * 512];
__device__ int   g_z   [B_];
__device__ uint2 g_keys[T_];
__device__ unsigned g_bcnt = 0;
__device__ unsigned g_bgen = 0;

// ---------------- grid barrier (proven) ----------------
__device__ __forceinline__ void gbar() {
    __syncthreads();
    if (threadIdx.x == 0) {
        unsigned gen = *((volatile unsigned*)&g_bgen);
        __threadfence();
        if (atomicAdd(&g_bcnt, 1u) == NB - 1u) {
            atomicExch(&g_bcnt, 0u);
            __threadfence();
            atomicAdd(&g_bgen, 1u);
        } else {
            while (*((volatile unsigned*)&g_bgen) == gen) { __nanosleep(32); }
        }
        __threadfence();
    }
    __syncthreads();
}

// ---------------- Threefry-2x32 (bit-exact, proven) ----------------
__device__ __forceinline__ void tf2x32(uint32_t k0, uint32_t k1,
                                       uint32_t x0, uint32_t x1,
                                       uint32_t& o0, uint32_t& o1) {
    uint32_t k2 = k0 ^ k1 ^ 0x1BD11BDAu;
    x0 += k0; x1 += k1;
#define RR(r) { x0 += x1; x1 = (x1 << (r)) | (x1 >> (32 - (r))); x1 ^= x0; }
    RR(13) RR(15) RR(26) RR(6)   x0 += k1; x1 += k2 + 1u;
    RR(17) RR(29) RR(16) RR(24)  x0 += k2; x1 += k0 + 2u;
    RR(13) RR(15) RR(26) RR(6)   x0 += k0; x1 += k1 + 3u;
    RR(17) RR(29) RR(16) RR(24)  x0 += k1; x1 += k2 + 4u;
    RR(13) RR(15) RR(26) RR(6)   x0 += k2; x1 += k0 + 5u;
#undef RR
    o0 = x0; o1 = x1;
}

__device__ __forceinline__ float bits_to_unit(uint32_t bits) {
    return __uint_as_float((bits >> 9) | 0x3f800000u) - 1.0f;
}

__device__ __forceinline__ float sigm(float x) { return 1.f / (1.f + expf(-x)); }

// ---------------- setup ----------------
__device__ void phase_setup(const float* __restrict__ phi_w, const float* __restrict__ psi_w,
                            const float* __restrict__ w_ih0,
                            const float* __restrict__ b_ih0, const float* __restrict__ b_hh0,
                            const float* __restrict__ b_ih1, const float* __restrict__ b_hh1,
                            const float* __restrict__ out_w, const int* __restrict__ y) {
    int gt = blockIdx.x * NT + threadIdx.x;
    for (int i = gt; i < 512 * 512; i += NTH) {
        int k = i >> 9, j = i & 511;
        g_psiT[i] = psi_w[j * 512 + k];
        g_phiT[i] = phi_w[j * 512 + k];
    }
    for (int i = gt; i < 64 * 2048; i += NTH) {
        int v = i >> 11, col = i & 2047, d = col >> 2, g = col & 3;
        g_ohI[i] = w_ih0[(g * 512 + d) * 576 + v];
    }
    for (int i = gt; i < 2048; i += NTH) {
        int d = i >> 2, g = i & 3;
        g_b0I[i] = b_ih0[g * 512 + d] + b_hh0[g * 512 + d];
        g_b1I[i] = b_ih1[g * 512 + d] + b_hh1[g * 512 + d];
    }
    for (int i = gt; i < 512 * 64; i += NTH) {
        int k = i >> 6, v = i & 63;
        g_outT[i] = out_w[v * 512 + k];
    }
    for (int i = gt; i < B_ * 1024; i += NTH) {
        g_XA[0][i] = 0.f; g_XA[1][i] = 0.f;
        g_XB[0][i] = 0.f; g_XB[1][i] = 0.f;
    }
    for (int i = gt; i < B_ * 512; i += NTH) {
        g_cs0[i] = 0.f; g_cs1[i] = 0.f; g_S1[i] = 0.f;
    }
    if (gt < T_) {
        uint32_t a, b;
        tf2x32(0u, 42u, 0u, (uint32_t)gt, a, b);
        g_keys[gt] = make_uint2(a, b);
    }
    if (gt < B_) g_z[gt] = y[gt * (T_ + 1)];
}

// ---------------- hp precompute: 64x64 tiles, reg prefetch ----------------
__device__ void gemm64(float* sbuf, const float* __restrict__ A,
                       const float* __restrict__ Bm, float* __restrict__ C,
                       const float* __restrict__ bias) {
    float (*As)[68] = (float(*)[68])sbuf;
    float (*Bs)[64] = (float(*)[64])(sbuf + 16 * 68);
    int tid = threadIdx.x;
    int r   = tid >> 2, kc = (tid & 3) << 2;
    int bkk = tid >> 4, bnc = (tid & 15) << 2;
    int tx  = tid & 15, ty = tid >> 4;
    for (int tile = blockIdx.x; tile < 1024 * 8; tile += NB) {
        int m0 = (tile >> 3) << 6;
        int n0 = (tile & 7) << 6;
        float acc[16];
#pragma unroll
        for (int i = 0; i < 16; i++) acc[i] = 0.f;
        const float* Ap = A + (size_t)(m0 + r) * 512 + kc;
        const float* Bp = Bm + (size_t)bkk * 512 + n0 + bnc;
        float4 av = *(const float4*)(Ap);
        float4 bv = *(const float4*)(Bp);
        for (int k0 = 0; k0 < 512; k0 += 16) {
            __syncthreads();
            As[kc][r] = av.x; As[kc + 1][r] = av.y;
            As[kc + 2][r] = av.z; As[kc + 3][r] = av.w;
            *(float4*)&Bs[bkk][bnc] = bv;
            __syncthreads();
            if (k0 + 16 < 512) {
                av = *(const float4*)(Ap + k0 + 16);
                bv = *(const float4*)(Bp + (size_t)(k0 + 16) * 512);
            }
#pragma unroll
            for (int kk = 0; kk < 16; kk++) {
                float4 a4 = *(const float4*)&As[kk][ty << 2];
                float4 b4 = *(const float4*)&Bs[kk][tx << 2];
                acc[0]  = fmaf(a4.x, b4.x, acc[0]);  acc[1]  = fmaf(a4.x, b4.y, acc[1]);
                acc[2]  = fmaf(a4.x, b4.z, acc[2]);  acc[3]  = fmaf(a4.x, b4.w, acc[3]);
                acc[4]  = fmaf(a4.y, b4.x, acc[4]);  acc[5]  = fmaf(a4.y, b4.y, acc[5]);
                acc[6]  = fmaf(a4.y, b4.z, acc[6]);  acc[7]  = fmaf(a4.y, b4.w, acc[7]);
                acc[8]  = fmaf(a4.z, b4.x, acc[8]);  acc[9]  = fmaf(a4.z, b4.y, acc[9]);
                acc[10] = fmaf(a4.z, b4.z, acc[10]); acc[11] = fmaf(a4.z, b4.w, acc[11]);
                acc[12] = fmaf(a4.w, b4.x, acc[12]); acc[13] = fmaf(a4.w, b4.y, acc[13]);
                acc[14] = fmaf(a4.w, b4.z, acc[14]); acc[15] = fmaf(a4.w, b4.w, acc[15]);
            }
        }
        float4 bb = *(const float4*)&bias[n0 + (tx << 2)];
#pragma unroll
        for (int i = 0; i < 4; i++) {
            float4 rr;
            rr.x = acc[i * 4 + 0] + bb.x; rr.y = acc[i * 4 + 1] + bb.y;
            rr.z = acc[i * 4 + 2] + bb.z; rr.w = acc[i * 4 + 3] + bb.w;
            *(float4*)&C[(size_t)(m0 + (ty << 2) + i) * 512 + n0 + (tx << 2)] = rr;
        }
    }
}

// ---------------- gates GEMM (128 x 16 cols, K=1024) + LSTM epilogue --------
// A staged ROW-major [row][20] (conflict-free LDS.128), double-buffered.
__device__ void gemm_gates(const float* __restrict__ A, const float* __restrict__ WIs,
                           float* As, const float* __restrict__ bI,
                           float* __restrict__ cs,
                           float* __restrict__ o1, int ld1,
                           float* __restrict__ o2, int ld2,
                           int n0, int layer0) {
    int tid = threadIdx.x;
    int ty = tid >> 2;
    int tx = tid & 3;
    int b0r = ty, b1r = ty + 64;
    int srow = tid >> 1, skoff = (tid & 1) << 3;
    float acc0[4] = {0.f,0.f,0.f,0.f}, acc1[4] = {0.f,0.f,0.f,0.f};
    const float* Arow = A + srow * 1024 + skoff;
    {
        float4 pa = *(const float4*)(Arow);
        float4 pb = *(const float4*)(Arow + 4);
        float* st = As + srow * 20 + skoff;
        *(float4*)(st) = pa; *(float4*)(st + 4) = pb;
    }
    for (int k0 = 0; k0 < 1024; k0 += 16) {
        int buf = (k0 >> 4) & 1;
        __syncthreads();
        if (k0 + 16 < 1024) {
            float4 pa = *(const float4*)(Arow + k0 + 16);
            float4 pb = *(const float4*)(Arow + k0 + 20);
            float* st = As + (buf ^ 1) * 2560 + srow * 20 + skoff;
            *(float4*)(st) = pa; *(float4*)(st + 4) = pb;
        }
        const float* Ab = As + buf * 2560;
#pragma unroll
        for (int k4 = 0; k4 < 16; k4 += 4) {
            float4 a0 = *(const float4*)&Ab[b0r * 20 + k4];
            float4 a1 = *(const float4*)&Ab[b1r * 20 + k4];
            float4 wv;
            wv = *(const float4*)&WIs[(k0 + k4 + 0) * 16 + (tx << 2)];
            acc0[0] = fmaf(a0.x, wv.x, acc0[0]); acc0[1] = fmaf(a0.x, wv.y, acc0[1]);
            acc0[2] = fmaf(a0.x, wv.z, acc0[2]); acc0[3] = fmaf(a0.x, wv.w, acc0[3]);
            acc1[0] = fmaf(a1.x, wv.x, acc1[0]); acc1[1] = fmaf(a1.x, wv.y, acc1[1]);
            acc1[2] = fmaf(a1.x, wv.z, acc1[2]); acc1[3] = fmaf(a1.x, wv.w, acc1[3]);
            wv = *(const float4*)&WIs[(k0 + k4 + 1) * 16 + (tx << 2)];
            acc0[0] = fmaf(a0.y, wv.x, acc0[0]); acc0[1] = fmaf(a0.y, wv.y, acc0[1]);
            acc0[2] = fmaf(a0.y, wv.z, acc0[2]); acc0[3] = fmaf(a0.y, wv.w, acc0[3]);
            acc1[0] = fmaf(a1.y, wv.x, acc1[0]); acc1[1] = fmaf(a1.y, wv.y, acc1[1]);
            acc1[2] = fmaf(a1.y, wv.z, acc1[2]); acc1[3] = fmaf(a1.y, wv.w, acc1[3]);
            wv = *(const float4*)&WIs[(k0 + k4 + 2) * 16 + (tx << 2)];
            acc0[0] = fmaf(a0.z, wv.x, acc0[0]); acc0[1] = fmaf(a0.z, wv.y, acc0[1]);
            acc0[2] = fmaf(a0.z, wv.z, acc0[2]); acc0[3] = fmaf(a0.z, wv.w, acc0[3]);
            acc1[0] = fmaf(a1.z, wv.x, acc1[0]); acc1[1] = fmaf(a1.z, wv.y, acc1[1]);
            acc1[2] = fmaf(a1.z, wv.z, acc1[2]); acc1[3] = fmaf(a1.z, wv.w, acc1[3]);
            wv = *(const float4*)&WIs[(k0 + k4 + 3) * 16 + (tx << 2)];
            acc0[0] = fmaf(a0.w, wv.x, acc0[0]); acc0[1] = fmaf(a0.w, wv.y, acc0[1]);
            acc0[2] = fmaf(a0.w, wv.z, acc0[2]); acc0[3] = fmaf(a0.w, wv.w, acc0[3]);
            acc1[0] = fmaf(a1.w, wv.x, acc1[0]); acc1[1] = fmaf(a1.w, wv.y, acc1[1]);
            acc1[2] = fmaf(a1.w, wv.z, acc1[2]); acc1[3] = fmaf(a1.w, wv.w, acc1[3]);
        }
    }
    int d = (n0 >> 2) + tx;
    float4 bb = *(const float4*)&bI[n0 + (tx << 2)];
#pragma unroll
    for (int i = 0; i < 2; i++) {
        int b = (i == 0) ? b0r : b1r;
        float* acc = (i == 0) ? acc0 : acc1;
        float gi = acc[0] + bb.x;
        float gf = acc[1] + bb.y;
        float gg = acc[2] + bb.z;
        float go = acc[3] + bb.w;
        if (layer0) {
            float4 oh = *(const float4*)&g_ohI[(size_t)g_z[b] * 2048 + n0 + (tx << 2)];
            gi += oh.x; gf += oh.y; gg += oh.z; go += oh.w;
        }
        float ii = sigm(gi), ff = sigm(gf), g2 = tanhf(gg), oo = sigm(go);
        float c = ff * cs[b * 512 + d] + ii * g2;
        cs[b * 512 + d] = c;
        float hh = oo * tanhf(c);
        o1[b * ld1 + d] = hh;
        o2[b * ld2 + d] = hh;
    }
}

// ---------------- q = s1 @ phiT + phi_b (block-local GEMV, L2-resident phiT) -
__device__ void qcompute(const float* __restrict__ phi_b,
                         float* __restrict__ qs, float* __restrict__ s1s) {
    int tid = threadIdx.x;
    int b = blockIdx.x;
    for (int i = tid; i < 512; i += NT) s1s[i] = g_S1[b * 512 + i];
    __syncthreads();
    float acc0 = phi_b[tid], acc1 = phi_b[tid + 256];
    const float* base = g_phiT + tid;
#pragma unroll 8
    for (int k = 0; k < 512; k++) {
        float sv = s1s[k];
        acc0 = fmaf(sv, base[(size_t)k * 512],       acc0);
        acc1 = fmaf(sv, base[(size_t)k * 512 + 256], acc1);
    }
    qs[tid] = acc0; qs[tid + 256] = acc1;
    __syncthreads();
}

// ---------------- attention: single pass, 4-row x depth-2 pipeline (R12) ----
#define ATT_LOAD4(V, ro) do {                                                 \
    const float* rp_ = hpw + (size_t)(ro) * 512;                              \
    _Pragma("unroll") for (int i_ = 0; i_ < 4; i_++)                          \
    _Pragma("unroll") for (int j_ = 0; j_ < 4; j_++)                          \
        V[i_][j_] = *(const float4*)(rp_ + i_ * 512 + j_ * 128 + (lane << 2));\
} while (0)

#define ATT_PROC4(V) do {                                                     \
    float dt_[4];                                                             \
    _Pragma("unroll") for (int i_ = 0; i_ < 4; i_++) {                        \
        float dd_ = 0.f;                                                      \
        _Pragma("unroll") for (int j_ = 0; j_ < 4; j_++) {                    \
            dd_ = fmaf(qf[j_].x, V[i_][j_].x, dd_);                           \
            dd_ = fmaf(qf[j_].y, V[i_][j_].y, dd_);                           \
            dd_ = fmaf(qf[j_].z, V[i_][j_].z, dd_);                           \
            dd_ = fmaf(qf[j_].w, V[i_][j_].w, dd_);                           \
        }                                                                     \
        dt_[i_] = dd_;                                                        \
    }                                                                         \
    _Pragma("unroll") for (int off_ = 16; off_ > 0; off_ >>= 1)               \
    _Pragma("unroll") for (int i_ = 0; i_ < 4; i_++)                          \
        dt_[i_] += __shfl_xor_sync(0xffffffffu, dt_[i_], off_);               \
    float mn_ = fmaxf(fmaxf(dt_[0], dt_[1]), fmaxf(dt_[2], dt_[3]));          \
    mn_ = fmaxf(m, mn_);                                                      \
    float corr_ = __expf(m - mn_);                                            \
    float p0_ = __expf(dt_[0] - mn_), p1_ = __expf(dt_[1] - mn_);             \
    float p2_ = __expf(dt_[2] - mn_), p3_ = __expf(dt_[3] - mn_);             \
    s = s * corr_ + (p0_ + p1_) + (p2_ + p3_);                                \
    _Pragma("unroll") for (int j_ = 0; j_ < 4; j_++) {                        \
        cacc[j_].x = fmaf(p3_, V[3][j_].x, fmaf(p2_, V[2][j_].x,              \
                     fmaf(p1_, V[1][j_].x, fmaf(p0_, V[0][j_].x, cacc[j_].x * corr_)))); \
        cacc[j_].y = fmaf(p3_, V[3][j_].y, fmaf(p2_, V[2][j_].y,              \
                     fmaf(p1_, V[1][j_].y, fmaf(p0_, V[0][j_].y, cacc[j_].y * corr_)))); \
        cacc[j_].z = fmaf(p3_, V[3][j_].z, fmaf(p2_, V[2][j_].z,              \
                     fmaf(p1_, V[1][j_].z, fmaf(p0_, V[0][j_].z, cacc[j_].z * corr_)))); \
        cacc[j_].w = fmaf(p3_, V[3][j_].w, fmaf(p2_, V[2][j_].w,              \
                     fmaf(p1_, V[1][j_].w, fmaf(p0_, V[0][j_].w, cacc[j_].w * corr_)))); \
    }                                                                         \
    m = mn_;                                                                  \
} while (0)

__device__ void attn_block(const float* __restrict__ qs, float* __restrict__ XAc) {
    __shared__ float sm_v[8][512];
    __shared__ float sm_ms[16];
    int b = blockIdx.x;
    int tid = threadIdx.x, lane = tid & 31, w = tid >> 5;
    float4 qf[4];
#pragma unroll
    for (int j = 0; j < 4; j++)
        qf[j] = *(const float4*)(qs + j * 128 + (lane << 2));
    const float* hpw = g_hp + (size_t)b * (R_ * HID_) + (size_t)w * 64 * 512;
    float m = -INFINITY, s = 0.f;
    float4 cacc[4];
#pragma unroll
    for (int j = 0; j < 4; j++) cacc[j] = make_float4(0.f, 0.f, 0.f, 0.f);

    float4 va[4][4], vb[4][4];
    ATT_LOAD4(va, 0);
    for (int p = 0; p < 16; p += 2) {
        ATT_LOAD4(vb, (p + 1) * 4);
        ATT_PROC4(va);
        if (p + 2 < 16) ATT_LOAD4(va, (p + 2) * 4);
        ATT_PROC4(vb);
    }
#pragma unroll
    for (int j = 0; j < 4; j++)
        *(float4*)&sm_v[w][j * 128 + (lane << 2)] = cacc[j];
    if (lane == 0) { sm_ms[w] = m; sm_ms[8 + w] = s; }
    __syncthreads();
    float M = sm_ms[0];
#pragma unroll
    for (int i = 1; i < 8; i++) M = fmaxf(M, sm_ms[i]);
    float we[8]; float S = 0.f;
#pragma unroll
    for (int i = 0; i < 8; i++) { we[i] = __expf(sm_ms[i] - M); S = fmaf(sm_ms[8 + i], we[i], S); }
    float inv = 1.f / S;
    for (int c = tid; c < 512; c += NT) {
        float a = 0.f;
#pragma unroll
        for (int i = 0; i < 8; i++) a = fmaf(we[i], sm_v[i][c], a);
        XAc[b * 1024 + c] = a * inv;
    }
}

// ---------------- logits + sampler for one batch row (bit-exact path) -------
__device__ void logits_sample_b(int t, int b, const float* __restrict__ out_b,
                                const int* __restrict__ y, float* __restrict__ out) {
    __shared__ float sl[4][64];
    __shared__ float sg2[64];
    int tid = threadIdx.x, v = tid & 63, part = tid >> 6;
    const float* s1 = g_S1 + b * 512 + part * 128;
    const float* ot = g_outT + part * 128 * 64 + v;
    float a0 = 0.f, a1 = 0.f;
#pragma unroll 4
    for (int k = 0; k < 128; k += 2) {
        a0 = fmaf(s1[k],     ot[k * 64],       a0);
        a1 = fmaf(s1[k + 1], ot[(k + 1) * 64], a1);
    }
    sl[part][v] = a0 + a1;
    __syncthreads();
    uint2 kt = g_keys[t];
    uint32_t k1a, k1b;
    tf2x32(kt.x, kt.y, 0u, 0u, k1a, k1b);
    if (tid < 64) {
        float logit = sl[0][tid] + sl[1][tid] + sl[2][tid] + sl[3][tid] + out_b[tid];
        out[((size_t)b * T_ + t) * VOC_ + tid] = logit;
        uint32_t r0, r1;
        tf2x32(k1a, k1b, 0u, (uint32_t)(b * VOC_ + tid), r0, r1);
        float f = bits_to_unit(r0 ^ r1);
        float u2 = fmaxf(f, 1.17549435e-38f);
        sg2[tid] = logit + (-logf(-logf(u2)));
    }
    __syncthreads();
    if (tid < 32) {
        float v0 = sg2[tid], v1 = sg2[tid + 32];
        int i0 = tid;
        if (v1 > v0) { v0 = v1; i0 = tid + 32; }
#pragma unroll
        for (int off = 16; off > 0; off >>= 1) {
            float ov = __shfl_down_sync(0xffffffffu, v0, off);
            int   oi = __shfl_down_sync(0xffffffffu, i0, off);
            if (ov > v0 || (ov == v0 && oi < i0)) { v0 = ov; i0 = oi; }
        }
        if (tid == 0) {
            uint32_t k2a, k2b, r0, r1;
            tf2x32(kt.x, kt.y, 0u, 1u, k2a, k2b);
            tf2x32(k2a, k2b, 0u, (uint32_t)b, r0, r1);
            float f = fmaxf(bits_to_unit(r0 ^ r1), 0.0f);
            g_z[b] = (f < 0.1f) ? i0 : y[b * (T_ + 1) + t + 1];
        }
    }
    __syncthreads();
}

// ============================================================================
__global__ void __launch_bounds__(NT, 1)
aas_persistent(const float* __restrict__ h,
               const float* __restrict__ phi_w, const float* __restrict__ phi_b,
               const float* __restrict__ psi_w, const float* __restrict__ psi_b,
               const float* __restrict__ w_ih0, const float* __restrict__ w_hh0,
               const float* __restrict__ b_ih0, const float* __restrict__ b_hh0,
               const float* __restrict__ w_ih1, const float* __restrict__ w_hh1,
               const float* __restrict__ b_ih1, const float* __restrict__ b_hh1,
               const float* __restrict__ out_w, const float* __restrict__ out_b,
               const int* __restrict__ y, float* __restrict__ out) {
    extern __shared__ float sbuf[];
    __shared__ float s1s[512], qs[512];
    int tid = threadIdx.x;
    int bx = blockIdx.x;

    phase_setup(phi_w, psi_w, w_ih0, b_ih0, b_hh0, b_ih1, b_hh1, out_w, y);
    gbar();

    gemm64(sbuf, h, g_psiT, g_hp, psi_b);    // hp = h @ psi^T + psi_b
    __syncthreads();                          // sbuf scratch done before residency

    if (bx < B_) {
        int n0 = bx * 16, d0 = n0 >> 2;
        float* WI0s = sbuf;
        float* WI1s = sbuf + 16384;
        for (int i = tid; i < 16 * 1024; i += NT) {
            int c = i >> 10, k = i & 1023;
            int g = c & 3, d = d0 + (c >> 2);
            int oc = g * 512 + d;
            WI0s[k * 16 + c] = (k < 512) ? w_ih0[oc * 576 + 64 + k]
                                         : w_hh0[oc * 512 + (k - 512)];
            WI1s[k * 16 + c] = (k < 512) ? w_ih1[oc * 512 + k]
                                         : w_hh1[oc * 512 + (k - 512)];
        }
    }
    gbar();

    float* AsG = sbuf + 32768;
    int n0 = bx * 16;

    for (int t = 0; t < T_; t++) {
        float* XAc = g_XA[t & 1];
        float* XAn = g_XA[(t + 1) & 1];
        float* XBc = g_XB[t & 1];
        float* XBn = g_XB[(t + 1) & 1];
        // phase 1: blocks 0-127: q GEMV + attention -> c into XAc[:, :512]
        //          blocks 128-147: logits + sampler for step t-1
        if (bx < B_) {
            qcompute(phi_b, qs, s1s);
            attn_block(qs, XAc);
        } else if (t > 0) {
            for (int b = bx - 128; b < B_; b += 20)
                logits_sample_b(t - 1, b, out_b, y, out);
        }
        gbar();
        // phase 2: gates0 + LSTM0 -> s0 into XBc[:, :512] and XAn[:, 512:]
        if (bx < B_)
            gemm_gates(XAc, sbuf, AsG, g_b0I, g_cs0, XBc, 1024, XAn + 512, 1024, n0, 1);
        gbar();
        // phase 3: gates1 + LSTM1 -> s1 into XBn[:, 512:] and S1
        if (bx < B_)
            gemm_gates(XBc, sbuf + 16384, AsG, g_b1I, g_cs1, XBn + 512, 1024, g_S1, 512, n0, 0);
        gbar();
    }
    // final step's logits + sampler output
    if (bx >= 128) {
        for (int b = bx - 128; b < B_; b += 20)
            logits_sample_b(T_ - 1, b, out_b, y, out);
    }
}

extern "C" void kernel_launch(void* const* d_in, const int* in_sizes, int n_in,
                              void* d_out, int out_size) {
    const float* h     = (const float*)d_in[0];
    const float* phi_w = (const float*)d_in[1];
    const float* phi_b = (const float*)d_in[2];
    const float* psi_w = (const float*)d_in[3];
    const float* psi_b = (const float*)d_in[4];
    const float* w_ih0 = (const float*)d_in[5];
    const float* w_hh0 = (const float*)d_in[6];
    const float* b_ih0 = (const float*)d_in[7];
    const float* b_hh0 = (const float*)d_in[8];
    const float* w_ih1 = (const float*)d_in[9];
    const float* w_hh1 = (const float*)d_in[10];
    const float* b_ih1 = (const float*)d_in[11];
    const float* b_hh1 = (const float*)d_in[12];
    const float* out_w = (const float*)d_in[13];
    const float* out_b = (const float*)d_in[14];
    const int*   y     = (const int*)d_in[15];
    float* out = (float*)d_out;

    cudaFuncSetAttribute(aas_persistent,
                         cudaFuncAttributeMaxDynamicSharedMemorySize, SMEM_DYN);
    aas_persistent<<<NB, NT, SMEM_DYN>>>(h, phi_w, phi_b, psi_w, psi_b,
                                         w_ih0, w_hh0, b_ih0, b_hh0,
                                         w_ih1, w_hh1, b_ih1, b_hh1,
                                         out_w, out_b, y, out);
}